// round 16
// baseline (speedup 1.0000x reference)
#include <cuda_runtime.h>
#include <cuda_fp16.h>
#include <cstdint>

#define B_     4096
#define N_IN   512
#define H1     1536
#define H2     1536
#define N_OUT  512
#define NODES  3584          // N_IN + H1 + H2
#define CAP    128           // bucket capacity per dst (Poisson(32), max ~66)
#define TBLOCKS 512          // 8 x 64 transpose tiles

typedef unsigned long long u64;

// ---------------- static device scratch (no allocations) ----------------
__device__ __align__(16) __half g_nvTh[NODES * B_];      // 29.4 MB node values, fp16
__device__ __align__(16) __half g_outTh[N_OUT * B_];     //  4.2 MB lvl3 result, fp16
__device__ int  g_cnt[NODES];        // zero at load; re-zeroed by transpose_out
__device__ __align__(16) int2 g_bpack[NODES * CAP];      // (src, w-bits); slots >= cnt stay 0

// ---------------- packed f32x2 helpers ----------------
__device__ __forceinline__ u64 pack2(float x, float y) {
    u64 r; asm("mov.b64 %0, {%1, %2};" : "=l"(r) : "f"(x), "f"(y)); return r;
}
__device__ __forceinline__ float2 unpack2(u64 v) {
    float2 f; asm("mov.b64 {%0, %1}, %2;" : "=f"(f.x), "=f"(f.y) : "l"(v)); return f;
}
__device__ __forceinline__ void ffma2(u64& acc, u64 a, u64 b) {
    asm("fma.rn.f32x2 %0, %1, %2, %0;" : "+l"(acc) : "l"(a), "l"(b));
}
__device__ __forceinline__ u64 cvt2(uint32_t h2) {
    float2 f = __half22float2(*reinterpret_cast<const __half2*>(&h2));
    return pack2(f.x, f.y);
}
__device__ __forceinline__ uint32_t smem_u32(const void* p) {
    uint32_t a;
    asm("{ .reg .u64 t; cvta.to.shared.u64 t, %1; cvt.u32.u64 %0, t; }" : "=r"(a) : "l"(p));
    return a;
}
__device__ __forceinline__ void cp_async16(uint32_t dst, const void* src) {
    asm volatile("cp.async.cg.shared.global [%0], [%1], 16;"
                 :: "r"(dst), "l"(__cvta_generic_to_global(src)));
}
#define CP_COMMIT()  asm volatile("cp.async.commit_group;" ::: "memory")
#define CP_WAIT1()   asm volatile("cp.async.wait_group 1;" ::: "memory")
__device__ __forceinline__ uint4 lds128(uint32_t a) {
    uint4 v;
    asm volatile("ld.shared.v4.u32 {%0,%1,%2,%3}, [%4];"
                 : "=r"(v.x), "=r"(v.y), "=r"(v.z), "=r"(v.w) : "r"(a));
    return v;
}

// ---------------- fused setup: transpose x -> fp16 nvT  +  bucket build ----
__global__ void setup_kernel(const float* __restrict__ x,
                             const int* __restrict__ src0, const int* __restrict__ dst0,
                             const float* __restrict__ w0, int E1,
                             const int* __restrict__ src1, const int* __restrict__ dst1,
                             const float* __restrict__ w1, int E2,
                             const int* __restrict__ src2, const int* __restrict__ dst2,
                             const float* __restrict__ w2, int E3) {
    const int tid = threadIdx.x;
    if (blockIdx.x < TBLOCKS) {
        __shared__ float tile[64][65];
        const int bx = (blockIdx.x & 7) * 64;    // node dim
        const int by = (blockIdx.x >> 3) * 64;   // batch dim
#pragma unroll
        for (int l = 0; l < 4; l++) {
            int i = tid + l * 256;
            int b = i >> 4, c4 = i & 15;
            float4 v = *reinterpret_cast<const float4*>(x + (size_t)(by + b) * N_IN + bx + c4 * 4);
            tile[b][c4 * 4 + 0] = v.x;
            tile[b][c4 * 4 + 1] = v.y;
            tile[b][c4 * 4 + 2] = v.z;
            tile[b][c4 * 4 + 3] = v.w;
        }
        __syncthreads();
#pragma unroll
        for (int l = 0; l < 2; l++) {
            int i = tid + l * 256;
            int n = i >> 3, g = i & 7;
            uint4 o; __half2 h;
            h = __floats2half2_rn(tile[g * 8 + 0][n], tile[g * 8 + 1][n]);
            o.x = *reinterpret_cast<uint32_t*>(&h);
            h = __floats2half2_rn(tile[g * 8 + 2][n], tile[g * 8 + 3][n]);
            o.y = *reinterpret_cast<uint32_t*>(&h);
            h = __floats2half2_rn(tile[g * 8 + 4][n], tile[g * 8 + 5][n]);
            o.z = *reinterpret_cast<uint32_t*>(&h);
            h = __floats2half2_rn(tile[g * 8 + 6][n], tile[g * 8 + 7][n]);
            o.w = *reinterpret_cast<uint32_t*>(&h);
            *reinterpret_cast<uint4*>(g_nvTh + (size_t)(bx + n) * B_ + by + g * 8) = o;
        }
        return;
    }
    // ---- bucket part: 2 consecutive edges per thread ----
    int i0 = ((blockIdx.x - TBLOCKS) * 256 + tid) * 2;
    const int Etot = E1 + E2 + E3;
    if (i0 >= Etot) return;
    const int *sp, *dp; const float* wp; int dbase, j0;
    if (i0 < E1)           { sp = src0; dp = dst0; wp = w0; dbase = 0;       j0 = i0; }
    else if (i0 < E1 + E2) { sp = src1; dp = dst1; wp = w1; dbase = H1;      j0 = i0 - E1; }
    else                   { sp = src2; dp = dst2; wp = w2; dbase = H1 + H2; j0 = i0 - E1 - E2; }
    int2   s = *reinterpret_cast<const int2*>(sp + j0);
    int2   d = *reinterpret_cast<const int2*>(dp + j0);
    float2 w = *reinterpret_cast<const float2*>(wp + j0);
    {
        int c = atomicAdd(&g_cnt[dbase + d.x], 1);
        if (c < CAP) g_bpack[(size_t)(dbase + d.x) * CAP + c] = make_int2(s.x, __float_as_int(w.x));
    }
    {
        int c = atomicAdd(&g_cnt[dbase + d.y], 1);
        if (c < CAP) g_bpack[(size_t)(dbase + d.y) * CAP + c] = make_int2(s.y, __float_as_int(w.y));
    }
}

// ---------------- output transpose (fp16 -> fp32) + cnt reset ----------------
__global__ void transpose_out_kernel(float* __restrict__ out) {
    if (blockIdx.x == 0 && blockIdx.y == 0) {
        for (int i = threadIdx.y * 32 + threadIdx.x; i < NODES; i += 256)
            g_cnt[i] = 0;
    }
    __shared__ float tile[32][33];
    const int bd = blockIdx.x * 32;
    const int bb = blockIdx.y * 32;
    const int tx = threadIdx.x, ty = threadIdx.y;
#pragma unroll
    for (int i = 0; i < 32; i += 8)
        tile[ty + i][tx] = __half2float(g_outTh[(size_t)(bd + ty + i) * B_ + bb + tx]);
    __syncthreads();
#pragma unroll
    for (int i = 0; i < 32; i += 8)
        out[(size_t)(bb + ty + i) * N_OUT + bd + tx] = tile[tx][ty + i];
}

// ---------------- cp.async-pipelined sparse level kernel ----------------
// One CTA per dst node; 256 threads; thread t owns cols [t*8, t*8+8) and
// [2048 + t*8, ...). 2-stage SMEM ring, 4 edges per stage. Each thread writes
// and reads ONLY its own smem slots -> no barriers in the loop;
// cp.async.wait_group gives per-thread visibility.
// Stage layout: slot(edge j, strip s, thread t) = ((j*2+s)*256 + t) * 16 bytes.
__device__ __forceinline__ void strip_fma(u64* a, u64 W, uint4 v) {
    ffma2(a[0], W, cvt2(v.x));
    ffma2(a[1], W, cvt2(v.y));
    ffma2(a[2], W, cvt2(v.z));
    ffma2(a[3], W, cvt2(v.w));
}

__global__ void __launch_bounds__(256)
level_pipe_kernel(int cbase, __half* __restrict__ outh) {
    extern __shared__ __align__(16) char smem[];
    const int d = blockIdx.x;
    const int t = threadIdx.x;

    int cnt = g_cnt[cbase + d];
    if (cnt > CAP) cnt = CAP;
    const int niter = (cnt + 3) >> 2;          // 4-edge blocks (zero-padded)
    const int2* bp = g_bpack + (size_t)(cbase + d) * CAP;

    const int c0 = t * 8;
    const __half* __restrict__ nvTh = g_nvTh;
    const uint32_t sA = smem_u32(smem) + (uint32_t)t * 16;   // stage 0, this thread
    const uint32_t sB = sA + 32768;                          // stage 1

    u64 acc[2][4];
#pragma unroll
    for (int s = 0; s < 2; s++)
#pragma unroll
        for (int j = 0; j < 4; j++) acc[s][j] = 0;

    // issue one stage: 4 edges x 2 strips = 8 cp.asyncs of 16B each
    auto issue_stage = [&](uint32_t base, int4 m0, int4 m1) {
        const __half* r0 = nvTh + (size_t)m0.x * B_ + c0;
        const __half* r1 = nvTh + (size_t)m0.z * B_ + c0;
        const __half* r2 = nvTh + (size_t)m1.x * B_ + c0;
        const __half* r3 = nvTh + (size_t)m1.z * B_ + c0;
        cp_async16(base + 0 * 4096, r0);
        cp_async16(base + 1 * 4096, r0 + 2048);
        cp_async16(base + 2 * 4096, r1);
        cp_async16(base + 3 * 4096, r1 + 2048);
        cp_async16(base + 4 * 4096, r2);
        cp_async16(base + 5 * 4096, r2 + 2048);
        cp_async16(base + 6 * 4096, r3);
        cp_async16(base + 7 * 4096, r3 + 2048);
    };

    int4 mA0, mA1, mB0, mB1;
    if (niter > 0) {
        mA0 = *reinterpret_cast<const int4*>(bp);
        mA1 = *reinterpret_cast<const int4*>(bp + 2);
        issue_stage(sA, mA0, mA1);
    }
    CP_COMMIT();                               // group 0 (stage 0)
    if (niter > 1) {
        mB0 = *reinterpret_cast<const int4*>(bp + 4);
        mB1 = *reinterpret_cast<const int4*>(bp + 6);
        issue_stage(sB, mB0, mB1);
    }
    CP_COMMIT();                               // group 1 (stage 1)

    for (int k = 0; k < niter; k++) {
        CP_WAIT1();                            // groups <= k complete
        const bool odd = (k & 1) != 0;
        const uint32_t base = odd ? sB : sA;
        const int4 m0 = odd ? mB0 : mA0;
        const int4 m1 = odd ? mB1 : mA1;

        // ---- compute stage k (pure LDS + cvt + FFMA2) ----
        {
            u64 W0 = pack2(__int_as_float(m0.y), __int_as_float(m0.y));
            u64 W1 = pack2(__int_as_float(m0.w), __int_as_float(m0.w));
            u64 W2 = pack2(__int_as_float(m1.y), __int_as_float(m1.y));
            u64 W3 = pack2(__int_as_float(m1.w), __int_as_float(m1.w));
            uint4 v;
            v = lds128(base + 0 * 4096); strip_fma(acc[0], W0, v);
            v = lds128(base + 1 * 4096); strip_fma(acc[1], W0, v);
            v = lds128(base + 2 * 4096); strip_fma(acc[0], W1, v);
            v = lds128(base + 3 * 4096); strip_fma(acc[1], W1, v);
            v = lds128(base + 4 * 4096); strip_fma(acc[0], W2, v);
            v = lds128(base + 5 * 4096); strip_fma(acc[1], W2, v);
            v = lds128(base + 6 * 4096); strip_fma(acc[0], W3, v);
            v = lds128(base + 7 * 4096); strip_fma(acc[1], W3, v);
        }

        // ---- refill this stage with block k+2 (safe: LDS above are done) ----
        if (k + 2 < niter) {
            int4 n0 = *reinterpret_cast<const int4*>(bp + 4 * (k + 2));
            int4 n1 = *reinterpret_cast<const int4*>(bp + 4 * (k + 2) + 2);
            if (odd) { mB0 = n0; mB1 = n1; }
            else     { mA0 = n0; mA1 = n1; }
            issue_stage(base, n0, n1);
        }
        CP_COMMIT();                           // keep group-count invariant
    }

    // ---- relu + fp16 store (zeros if no edges — required, rows are stale) ----
#pragma unroll
    for (int s = 0; s < 2; s++) {
        float r[8];
#pragma unroll
        for (int j = 0; j < 4; j++) {
            float2 f = unpack2(acc[s][j]);
            r[2 * j]     = fmaxf(f.x, 0.f);
            r[2 * j + 1] = fmaxf(f.y, 0.f);
        }
        uint4 o; __half2 h;
        h = __floats2half2_rn(r[0], r[1]); o.x = *reinterpret_cast<uint32_t*>(&h);
        h = __floats2half2_rn(r[2], r[3]); o.y = *reinterpret_cast<uint32_t*>(&h);
        h = __floats2half2_rn(r[4], r[5]); o.z = *reinterpret_cast<uint32_t*>(&h);
        h = __floats2half2_rn(r[6], r[7]); o.w = *reinterpret_cast<uint32_t*>(&h);
        *reinterpret_cast<uint4*>(outh + (size_t)d * B_ + c0 + s * 2048) = o;
    }
}

// ---------------- launch ----------------
extern "C" void kernel_launch(void* const* d_in, const int* in_sizes, int n_in,
                              void* d_out, int out_size) {
    const float* x    = (const float*)d_in[0];
    const int*   src0 = (const int*)  d_in[1];
    const int*   dst0 = (const int*)  d_in[2];
    const float* w0   = (const float*)d_in[3];
    const int*   src1 = (const int*)  d_in[4];
    const int*   dst1 = (const int*)  d_in[5];
    const float* w1   = (const float*)d_in[6];
    const int*   src2 = (const int*)  d_in[7];
    const int*   dst2 = (const int*)  d_in[8];
    const float* w2   = (const float*)d_in[9];
    float* out = (float*)d_out;

    __half* pnvTh;  cudaGetSymbolAddress((void**)&pnvTh,  g_nvTh);
    __half* poutTh; cudaGetSymbolAddress((void**)&poutTh, g_outTh);

    const int E1 = in_sizes[1], E2 = in_sizes[4], E3 = in_sizes[7];
    const int Etot = E1 + E2 + E3;

    constexpr int SMEM = 2 * 32768;   // 64 KB ring
    cudaFuncSetAttribute(level_pipe_kernel, cudaFuncAttributeMaxDynamicSharedMemorySize, SMEM);

    // 1) fused setup: vectorized x transpose + bucket build
    {
        int bucketBlocks = (Etot / 2 + 255) / 256;
        setup_kernel<<<TBLOCKS + bucketBlocks, 256>>>(
            x, src0, dst0, w0, E1, src1, dst1, w1, E2, src2, dst2, w2, E3);
    }

    // 2) pipelined sparse levels (one CTA per dst node)
    level_pipe_kernel<<<H1, 256, SMEM>>>(0,  pnvTh + (size_t)N_IN * B_);
    level_pipe_kernel<<<H2, 256, SMEM>>>(H1, pnvTh + (size_t)(N_IN + H1) * B_);
    level_pipe_kernel<<<N_OUT, 256, SMEM>>>(H1 + H2, poutTh);

    // 3) transpose fp16 result to fp32 [B, N_OUT] (+ reset g_cnt for next call)
    transpose_out_kernel<<<dim3(N_OUT / 32, B_ / 32), dim3(32, 8)>>>(out);
}